// round 3
// baseline (speedup 1.0000x reference)
#include <cuda_runtime.h>
#include <cuda_bf16.h>
#include <math.h>

// ---------------- problem constants ----------------
#define L_TOK 10000
#define LP    10048          // 157 * 64 (padded length)
#define NC    157            // chunks
#define Q     64             // chunk length
#define DM    512
#define DI    1024
#define DS    64
#define NH    16
#define HD    64
#define DXBC  1152
#define DPROJ 2192
#define NB    3              // branches

// ---------------- scratch (device globals, no allocation) ----------------
__device__ __align__(16) float g_hbase[(size_t)L_TOK*DM];
__device__ __align__(16) float g_hcur [(size_t)NB*LP*DM];
__device__ __align__(16) float g_zx   [(size_t)NB*LP*DPROJ];
__device__ __align__(16) float g_xs   [(size_t)NB*LP*DI];
__device__ __align__(16) float g_Bm   [(size_t)NB*LP*DS];
__device__ __align__(16) float g_Cm   [(size_t)NB*LP*DS];
__device__ __align__(16) float g_dtv  [(size_t)NB*LP*NH];
__device__ __align__(16) float g_av   [(size_t)NB*NH*LP];
__device__ __align__(16) float g_cum  [(size_t)NB*NH*LP];
__device__ __align__(16) float g_y    [(size_t)NB*LP*DI];
__device__ __align__(16) float g_schunk[(size_t)NB*NH*NC*DS*HD];
__device__ __align__(16) float g_sbef  [(size_t)NB*NH*NC*DS*HD];
__device__ __align__(16) float g_hn   [(size_t)NB*L_TOK*DM];
__device__ __align__(16) float g_s1   [(size_t)NB*L_TOK*128];
__device__ float g_scoreb[NB*L_TOK];
__device__ float g_wts   [NB*L_TOK];
__device__ float g_pooled[DM];

// ---------------- helpers ----------------
__device__ __forceinline__ float bsum(float v) {
    __shared__ float sh[32];
    int lane = threadIdx.x & 31, w = threadIdx.x >> 5;
    #pragma unroll
    for (int o = 16; o > 0; o >>= 1) v += __shfl_xor_sync(0xffffffffu, v, o);
    if (lane == 0) sh[w] = v;
    __syncthreads();
    int nw = blockDim.x >> 5;
    v = (threadIdx.x < nw) ? sh[threadIdx.x] : 0.f;
    if (w == 0) {
        #pragma unroll
        for (int o = 16; o > 0; o >>= 1) v += __shfl_xor_sync(0xffffffffu, v, o);
        if (threadIdx.x == 0) sh[0] = v;
    }
    __syncthreads();
    float r = sh[0];
    __syncthreads();
    return r;
}

// ---------------- tf32 split + mma helpers ----------------
__device__ __forceinline__ float2 split_tf32_f2(float v) {
    unsigned h;
    asm("cvt.rna.tf32.f32 %0, %1;" : "=r"(h) : "f"(v));
    float lf = v - __uint_as_float(h);
    unsigned l;
    asm("cvt.rna.tf32.f32 %0, %1;" : "=r"(l) : "f"(lf));
    return make_float2(__uint_as_float(h), __uint_as_float(l));
}

__device__ __forceinline__ void mma8(float c[4], const unsigned a[4], const unsigned b[2]) {
    asm volatile(
        "mma.sync.aligned.m16n8k8.row.col.f32.tf32.tf32.f32 "
        "{%0,%1,%2,%3},{%4,%5,%6,%7},{%8,%9},{%0,%1,%2,%3};"
        : "+f"(c[0]), "+f"(c[1]), "+f"(c[2]), "+f"(c[3])
        : "r"(a[0]), "r"(a[1]), "r"(a[2]), "r"(a[3]), "r"(b[0]), "r"(b[1]));
}

// ---------------- tensor-core GEMM: C = A(MxK) @ W(NxK)^T (3xTF32) ----------------
// (hi,lo) tf32 pairs pre-split into smem at tile load; inner loop is pure LDS.64 + MMA.
// op: 0 = store, 1 = C += , 2 = relu(v+bias), 3 = tanh(v+bias)
// per-z: A += z*sA, C += z*sC, W += (2*z+joff)*sW
// tiles: BM=128, BN=64, BK=16, 256 threads = 8 warps (4 m-warps x 2 n-warps)
#define APAD2 132
#define WPAD2 68
__global__ __launch_bounds__(256, 2) void tgemm(
    const float* __restrict__ A, long long sA,
    const float* __restrict__ W, long long sW,
    const float* __restrict__ bias,
    float* __restrict__ C, long long sC,
    int M, int N, int K, int op, int joff)
{
    int z = blockIdx.z;
    A += (long long)z * sA;
    C += (long long)z * sC;
    W += (long long)(2 * z + joff) * sW;

    __shared__ float2 As[2][16][APAD2];
    __shared__ float2 Ws[2][16][WPAD2];

    int tid = threadIdx.x;
    int warp = tid >> 5, lane = tid & 31;
    int wm = warp & 3, wn = warp >> 2;
    int g = lane >> 2, tig = lane & 3;
    int row0 = blockIdx.y * 128, col0 = blockIdx.x * 64;

    // ldg indexing
    int ar = tid >> 1, ak = (tid & 1) * 8;        // A: row, k-offset (8 floats)
    int wr = tid >> 2, wk = (tid & 3) * 4;        // W: row(n), k-offset (4 floats)
    bool aok = (row0 + ar) < M;
    bool wok = (col0 + wr) < N;
    const float* Aptr = A + (long long)(row0 + ar) * K + ak;
    const float* Wptr = W + (long long)(col0 + wr) * K + wk;

    float c[2][4][4];
    #pragma unroll
    for (int mt = 0; mt < 2; mt++)
        #pragma unroll
        for (int nt = 0; nt < 4; nt++)
            #pragma unroll
            for (int q = 0; q < 4; q++) c[mt][nt][q] = 0.f;

    float4 pa0, pa1, pw;
    const float4 zero4 = make_float4(0.f, 0.f, 0.f, 0.f);

    // load tile 0 (split to (hi,lo) pairs at store time)
    pa0 = aok ? *(const float4*)(Aptr)     : zero4;
    pa1 = aok ? *(const float4*)(Aptr + 4) : zero4;
    pw  = wok ? *(const float4*)(Wptr)     : zero4;
    {
        float fa[8] = {pa0.x, pa0.y, pa0.z, pa0.w, pa1.x, pa1.y, pa1.z, pa1.w};
        #pragma unroll
        for (int i = 0; i < 8; i++) As[0][ak + i][ar] = split_tf32_f2(fa[i]);
        float fw[4] = {pw.x, pw.y, pw.z, pw.w};
        #pragma unroll
        for (int i = 0; i < 4; i++) Ws[0][wk + i][wr] = split_tf32_f2(fw[i]);
    }
    __syncthreads();

    int nK = K >> 4;
    for (int kt = 0; kt < nK; kt++) {
        int cur = kt & 1;
        bool pf = (kt + 1) < nK;
        if (pf) {
            const float* Ap = Aptr + (kt + 1) * 16;
            const float* Wp = Wptr + (kt + 1) * 16;
            pa0 = aok ? *(const float4*)(Ap)     : zero4;
            pa1 = aok ? *(const float4*)(Ap + 4) : zero4;
            pw  = wok ? *(const float4*)(Wp)     : zero4;
        }

        #pragma unroll
        for (int ks = 0; ks < 2; ks++) {
            int k0 = ks * 8;
            float2 afr[2][4];
            #pragma unroll
            for (int mt = 0; mt < 2; mt++) {
                int m0 = wm * 32 + mt * 16;
                afr[mt][0] = As[cur][k0 + tig    ][m0 + g    ];
                afr[mt][1] = As[cur][k0 + tig    ][m0 + g + 8];
                afr[mt][2] = As[cur][k0 + tig + 4][m0 + g    ];
                afr[mt][3] = As[cur][k0 + tig + 4][m0 + g + 8];
            }
            float2 bfr[4][2];
            #pragma unroll
            for (int nt = 0; nt < 4; nt++) {
                int n0 = wn * 32 + nt * 8;
                bfr[nt][0] = Ws[cur][k0 + tig    ][n0 + g];
                bfr[nt][1] = Ws[cur][k0 + tig + 4][n0 + g];
            }
            unsigned ahi[2][4], alo[2][4];
            #pragma unroll
            for (int mt = 0; mt < 2; mt++)
                #pragma unroll
                for (int q = 0; q < 4; q++) {
                    ahi[mt][q] = __float_as_uint(afr[mt][q].x);
                    alo[mt][q] = __float_as_uint(afr[mt][q].y);
                }
            unsigned bhi[4][2], blo[4][2];
            #pragma unroll
            for (int nt = 0; nt < 4; nt++)
                #pragma unroll
                for (int q = 0; q < 2; q++) {
                    bhi[nt][q] = __float_as_uint(bfr[nt][q].x);
                    blo[nt][q] = __float_as_uint(bfr[nt][q].y);
                }
            #pragma unroll
            for (int mt = 0; mt < 2; mt++)
                #pragma unroll
                for (int nt = 0; nt < 4; nt++) {
                    mma8(c[mt][nt], alo[mt], bhi[nt]);
                    mma8(c[mt][nt], ahi[mt], blo[nt]);
                    mma8(c[mt][nt], ahi[mt], bhi[nt]);
                }
        }

        if (pf) {
            int nxt = 1 - cur;
            float fa[8] = {pa0.x, pa0.y, pa0.z, pa0.w, pa1.x, pa1.y, pa1.z, pa1.w};
            #pragma unroll
            for (int i = 0; i < 8; i++) As[nxt][ak + i][ar] = split_tf32_f2(fa[i]);
            float fw[4] = {pw.x, pw.y, pw.z, pw.w};
            #pragma unroll
            for (int i = 0; i < 4; i++) Ws[nxt][wk + i][wr] = split_tf32_f2(fw[i]);
            __syncthreads();
        }
    }

    // epilogue
    #pragma unroll
    for (int mt = 0; mt < 2; mt++) {
        #pragma unroll
        for (int nt = 0; nt < 4; nt++) {
            int cc = col0 + wn * 32 + nt * 8 + 2 * tig;
            if (cc >= N) continue;
            #pragma unroll
            for (int half = 0; half < 2; half++) {
                int r = row0 + wm * 32 + mt * 16 + g + half * 8;
                if (r >= M) continue;
                float v0 = c[mt][nt][half * 2 + 0];
                float v1 = c[mt][nt][half * 2 + 1];
                long long ci = (long long)r * N + cc;
                if (op == 0) {
                    *(float2*)&C[ci] = make_float2(v0, v1);
                } else if (op == 1) {
                    float2 o = *(float2*)&C[ci];
                    o.x += v0; o.y += v1;
                    *(float2*)&C[ci] = o;
                } else if (op == 2) {
                    v0 += bias[cc]; v1 += bias[cc + 1];
                    *(float2*)&C[ci] = make_float2(v0 > 0.f ? v0 : 0.f, v1 > 0.f ? v1 : 0.f);
                } else {
                    v0 += bias[cc]; v1 += bias[cc + 1];
                    *(float2*)&C[ci] = make_float2(tanhf(v0), tanhf(v1));
                }
            }
        }
    }
}

// ---------------- prep: build 3 branch inputs ----------------
__global__ void k_prep(const float* __restrict__ hb, float* __restrict__ hcur) {
    long long i = (long long)blockIdx.x * 256 + threadIdx.x;
    if (i >= (long long)L_TOK * DM) return;
    int t = (int)(i >> 9);
    int d = (int)(i & 511);
    float v = hb[i];
    hcur[(long long)t * DM + d] = v;                                      // branch 0
    hcur[(long long)LP * DM + (long long)t * DM + (DM - 1 - d)] = v;      // branch 1: feature flip
    int tt = (t % 100) * 100 + t / 100;                                   // branch 2: grid transpose
    hcur[2LL * LP * DM + (long long)tt * DM + d] = v;
}

__global__ void k_zeropad(float* __restrict__ hcur) {
    int i = blockIdx.x * 256 + threadIdx.x;
    const int tot = NB * (LP - L_TOK) * DM;
    if (i >= tot) return;
    int b = i / ((LP - L_TOK) * DM);
    int r = i % ((LP - L_TOK) * DM);
    hcur[(long long)b * LP * DM + (long long)L_TOK * DM + r] = 0.f;
}

// ---------------- depthwise causal conv + silu + split ----------------
__global__ void k_conv(const float* __restrict__ cw, const float* __restrict__ cb, int j) {
    int t = blockIdx.x, b = blockIdx.y;
    int lidx = 2 * b + j;
    const float* base = g_zx + (long long)b * LP * DPROJ + DI;  // xBC slice
    long long tb = (long long)b * LP + t;
    for (int c = threadIdx.x; c < DXBC; c += blockDim.x) {
        float accv = cb[lidx * DXBC + c];
        #pragma unroll
        for (int k = 0; k < 4; k++) {
            int ttk = t - 3 + k;
            if (ttk >= 0)
                accv += base[(long long)ttk * DPROJ + c] * cw[(lidx * DXBC + c) * 4 + k];
        }
        float v = accv / (1.f + __expf(-accv));
        if (t >= L_TOK) v = 0.f;
        if (c < DI)            g_xs[tb * DI + c] = v;
        else if (c < DI + DS)  g_Bm[tb * DS + (c - DI)] = v;
        else                   g_Cm[tb * DS + (c - DI - DS)] = v;
    }
}

// ---------------- dt = softplus(dt_raw + bias), a = dt * A ----------------
__global__ void k_dt(const float* __restrict__ dt_bias, const float* __restrict__ A_log, int j) {
    long long idx = (long long)blockIdx.x * 256 + threadIdx.x;
    if (idx >= (long long)NB * LP * NH) return;
    int hd = (int)(idx % NH);
    int t  = (int)((idx / NH) % LP);
    int b  = (int)(idx / ((long long)NH * LP));
    int lidx = 2 * b + j;
    float draw = g_zx[((long long)b * LP + t) * DPROJ + DI + DXBC + hd];
    float xv = draw + dt_bias[lidx * NH + hd];
    float sp = (xv > 20.f) ? xv : log1pf(expf(xv));
    if (t >= L_TOK) sp = 0.f;
    float Ah = -expf(A_log[lidx * NH + hd]);
    g_dtv[((long long)b * LP + t) * NH + hd] = sp;
    g_av[((long long)(b * NH + hd)) * LP + t] = sp * Ah;
}

// ---------------- per-chunk inclusive cumsum of a ----------------
__global__ void k_cumsum() {
    int c = blockIdx.x, h = blockIdx.y, b = blockIdx.z;
    long long base = (long long)(b * NH + h) * LP + (long long)c * Q;
    int t = threadIdx.x;  // 64 threads
    float x = g_av[base + t];
    #pragma unroll
    for (int o = 1; o < 32; o <<= 1) {
        float yv = __shfl_up_sync(0xffffffffu, x, o);
        if ((t & 31) >= o) x += yv;
    }
    __shared__ float w0;
    if (t == 31) w0 = x;
    __syncthreads();
    if (t >= 32) x += w0;
    g_cum[base + t] = x;
}

#define SMEM_INTRA ((4 * 64 * 65 + 64) * 4)

// ---------------- intra-chunk attention-like kernel + chunk state ----------------
__global__ __launch_bounds__(256) void k_intra() {
    extern __shared__ float sm[];
    float* sC   = sm;
    float* sB   = sm + 64 * 65;
    float* sU   = sm + 2 * 64 * 65;
    float* sP   = sm + 3 * 64 * 65;
    float* scum = sm + 4 * 64 * 65;

    int c = blockIdx.x, h = blockIdx.y, b = blockIdx.z;
    long long rowb = (long long)b * LP + (long long)c * Q;
    int tid = threadIdx.x;

    for (int i = tid; i < 4096; i += 256) {
        int t = i >> 6, n = i & 63;
        sC[t * 65 + n] = g_Cm[(rowb + t) * DS + n];
        sB[t * 65 + n] = g_Bm[(rowb + t) * DS + n];
        sU[t * 65 + n] = g_dtv[(rowb + t) * NH + h] * g_xs[(rowb + t) * DI + h * HD + n];
    }
    if (tid < 64) scum[tid] = g_cum[(long long)(b * NH + h) * LP + (long long)c * Q + tid];
    __syncthreads();

    int tx = tid & 15, ty = tid >> 4;
    int r0 = ty * 4, c0 = tx * 4;

    // P = mask(exp) * (C @ B^T)
    {
        float acc[4][4];
        #pragma unroll
        for (int i = 0; i < 4; i++) { acc[i][0]=0.f; acc[i][1]=0.f; acc[i][2]=0.f; acc[i][3]=0.f; }
        for (int n = 0; n < 64; n++) {
            float cv[4], bv[4];
            #pragma unroll
            for (int i = 0; i < 4; i++) cv[i] = sC[(r0 + i) * 65 + n];
            #pragma unroll
            for (int j = 0; j < 4; j++) bv[j] = sB[(c0 + j) * 65 + n];
            #pragma unroll
            for (int i = 0; i < 4; i++)
                #pragma unroll
                for (int j = 0; j < 4; j++) acc[i][j] += cv[i] * bv[j];
        }
        #pragma unroll
        for (int i = 0; i < 4; i++)
            #pragma unroll
            for (int j = 0; j < 4; j++) {
                int t = r0 + i, s = c0 + j;
                sP[t * 65 + s] = (s <= t) ? acc[i][j] * __expf(scum[t] - scum[s]) : 0.f;
            }
    }
    __syncthreads();

    // Y_intra = P @ U
    {
        float accY[4][4];
        #pragma unroll
        for (int i = 0; i < 4; i++) { accY[i][0]=0.f; accY[i][1]=0.f; accY[i][2]=0.f; accY[i][3]=0.f; }
        for (int s = 0; s < 64; s++) {
            float pv[4], uv[4];
            #pragma unroll
            for (int i = 0; i < 4; i++) pv[i] = sP[(r0 + i) * 65 + s];
            #pragma unroll
            for (int j = 0; j < 4; j++) uv[j] = sU[s * 65 + c0 + j];
            #pragma unroll
            for (int i = 0; i < 4; i++)
                #pragma unroll
                for (int j = 0; j < 4; j++) accY[i][j] += pv[i] * uv[j];
        }
        #pragma unroll
        for (int i = 0; i < 4; i++)
            #pragma unroll
            for (int j = 0; j < 4; j++)
                g_y[(rowb + r0 + i) * DI + h * HD + c0 + j] = accY[i][j];
    }

    // S_chunk[n][p] = sum_s exp(T - cum_s) B[s][n] U[s][p]
    {
        float T = scum[63];
        float accS[4][4];
        #pragma unroll
        for (int i = 0; i < 4; i++) { accS[i][0]=0.f; accS[i][1]=0.f; accS[i][2]=0.f; accS[i][3]=0.f; }
        for (int s = 0; s < 64; s++) {
            float w = __expf(T - scum[s]);
            float bv[4], uv[4];
            #pragma unroll
            for (int i = 0; i < 4; i++) bv[i] = sB[s * 65 + r0 + i] * w;
            #pragma unroll
            for (int j = 0; j < 4; j++) uv[j] = sU[s * 65 + c0 + j];
            #pragma unroll
            for (int i = 0; i < 4; i++)
                #pragma unroll
                for (int j = 0; j < 4; j++) accS[i][j] += bv[i] * uv[j];
        }
        long long sbase = ((long long)(b * NH + h) * NC + c) * 4096;
        #pragma unroll
        for (int i = 0; i < 4; i++)
            #pragma unroll
            for (int j = 0; j < 4; j++)
                g_schunk[sbase + (r0 + i) * 64 + c0 + j] = accS[i][j];
    }
}

// ---------------- sequential chunk-state recurrence (only sequential part) ----------------
__global__ __launch_bounds__(256) void k_rec() {
    int bh = blockIdx.x;          // 0..47
    int tid = threadIdx.x;        // 256
    float S[16];
    #pragma unroll
    for (int i = 0; i < 16; i++) S[i] = 0.f;
    const float* cumrow = g_cum + (long long)bh * LP;
    for (int c = 0; c < NC; c++) {
        long long base = ((long long)bh * NC + c) * 4096;
        float e = __expf(cumrow[c * Q + 63]);
        #pragma unroll
        for (int i = 0; i < 16; i++) {
            int idx = tid + i * 256;
            g_sbef[base + idx] = S[i];
            S[i] = e * S[i] + g_schunk[base + idx];
        }
    }
}

// ---------------- inter-chunk contribution + Dh*x ----------------
__global__ __launch_bounds__(256) void k_inter(const float* __restrict__ Dh, int j) {
    __shared__ float sS[64 * 65];
    __shared__ float sC[64 * 65];
    __shared__ float scum[64];
    int c = blockIdx.x, h = blockIdx.y, b = blockIdx.z;
    long long rowb = (long long)b * LP + (long long)c * Q;
    int tid = threadIdx.x;
    long long sbase = ((long long)(b * NH + h) * NC + c) * 4096;
    for (int i = tid; i < 4096; i += 256) {
        int r = i >> 6, n = i & 63;
        sS[r * 65 + n] = g_sbef[sbase + i];
        sC[r * 65 + n] = g_Cm[(rowb + r) * DS + n];
    }
    if (tid < 64) scum[tid] = g_cum[(long long)(b * NH + h) * LP + (long long)c * Q + tid];
    __syncthreads();

    int tx = tid & 15, ty = tid >> 4;
    int r0 = ty * 4, c0 = tx * 4;
    float acc[4][4];
    #pragma unroll
    for (int i = 0; i < 4; i++) { acc[i][0]=0.f; acc[i][1]=0.f; acc[i][2]=0.f; acc[i][3]=0.f; }
    for (int n = 0; n < 64; n++) {
        float cv[4], sv[4];
        #pragma unroll
        for (int i = 0; i < 4; i++) cv[i] = sC[(r0 + i) * 65 + n];
        #pragma unroll
        for (int jj = 0; jj < 4; jj++) sv[jj] = sS[n * 65 + c0 + jj];
        #pragma unroll
        for (int i = 0; i < 4; i++)
            #pragma unroll
            for (int jj = 0; jj < 4; jj++) acc[i][jj] += cv[i] * sv[jj];
    }
    float dh = Dh[(2 * b + j) * NH + h];
    #pragma unroll
    for (int i = 0; i < 4; i++) {
        float e = __expf(scum[r0 + i]);
        #pragma unroll
        for (int jj = 0; jj < 4; jj++) {
            long long ydx = (rowb + r0 + i) * DI + h * HD + c0 + jj;
            g_y[ydx] = g_y[ydx] + e * acc[i][jj] + dh * g_xs[ydx];
        }
    }
}

// ---------------- gate (silu(z)) + RMSNorm, in place on g_y ----------------
__global__ __launch_bounds__(256) void k_gate(const float* __restrict__ norm_w, int j) {
    int t = blockIdx.x, b = blockIdx.y;
    int lidx = 2 * b + j;
    const float* z = g_zx + ((long long)b * LP + t) * DPROJ;
    float* yr = g_y + ((long long)b * LP + t) * DI;
    float vals[4];
    float ss = 0.f;
    #pragma unroll
    for (int i = 0; i < 4; i++) {
        int cidx = threadIdx.x + i * 256;
        float zv = z[cidx];
        float gv = yr[cidx] * (zv / (1.f + __expf(-zv)));
        vals[i] = gv;
        ss += gv * gv;
    }
    float tot = bsum(ss);
    float scale = rsqrtf(tot / (float)DI + 1e-5f);
    #pragma unroll
    for (int i = 0; i < 4; i++) {
        int cidx = threadIdx.x + i * 256;
        yr[cidx] = vals[i] * scale * norm_w[lidx * DI + cidx];
    }
}

// ---------------- final LayerNorm over concat tokens ----------------
__global__ __launch_bounds__(256) void k_ln(const float* __restrict__ lnw, const float* __restrict__ lnb) {
    int g = blockIdx.x;          // 0..29999
    int b = g / L_TOK, t = g % L_TOK;
    const float* row = g_hcur + ((long long)b * LP + t) * DM;
    int tid = threadIdx.x;
    float v0 = row[tid], v1 = row[tid + 256];
    float s = bsum(v0 + v1);
    float sq = bsum(v0 * v0 + v1 * v1);
    float mu = s / (float)DM;
    float var = sq / (float)DM - mu * mu;
    float inv = rsqrtf(var + 1e-5f);
    g_hn[(long long)g * DM + tid]       = (v0 - mu) * inv * lnw[tid] + lnb[tid];
    g_hn[(long long)g * DM + tid + 256] = (v1 - mu) * inv * lnw[tid + 256] + lnb[tid + 256];
}

// ---------------- attention scalar score ----------------
__global__ void k_score(const float* __restrict__ w2, const float* __restrict__ b2) {
    int g = blockIdx.x;
    int tid = threadIdx.x;  // 128
    float v = g_s1[(long long)g * 128 + tid] * w2[tid];
    v = bsum(v);
    if (tid == 0) g_scoreb[g] = v + b2[0];
}

// ---------------- softmax over 30000 scores ----------------
__global__ void k_softmax() {
    const int n = NB * L_TOK;
    __shared__ float red[32];
    __shared__ float s_max, s_sum;
    int tid = threadIdx.x;  // 1024
    float m = -1e30f;
    for (int i = tid; i < n; i += 1024) m = fmaxf(m, g_scoreb[i]);
    #pragma unroll
    for (int o = 16; o > 0; o >>= 1) m = fmaxf(m, __shfl_xor_sync(0xffffffffu, m, o));
    if ((tid & 31) == 0) red[tid >> 5] = m;
    __syncthreads();
    if (tid < 32) {
        float v = red[tid];
        #pragma unroll
        for (int o = 16; o > 0; o >>= 1) v = fmaxf(v, __shfl_xor_sync(0xffffffffu, v, o));
        if (tid == 0) s_max = v;
    }
    __syncthreads();
    float m0 = s_max;
    float s = 0.f;
    for (int i = tid; i < n; i += 1024) s += expf(g_scoreb[i] - m0);
    #pragma unroll
    for (int o = 16; o > 0; o >>= 1) s += __shfl_xor_sync(0xffffffffu, s, o);
    if ((tid & 31) == 0) red[tid >> 5] = s;
    __syncthreads();
    if (tid < 32) {
        float v = red[tid];
        #pragma unroll
        for (int o = 16; o > 0; o >>= 1) v += __shfl_xor_sync(0xffffffffu, v, o);
        if (tid == 0) s_sum = v;
    }
    __syncthreads();
    float inv = 1.f / s_sum;
    for (int i = tid; i < n; i += 1024) g_wts[i] = expf(g_scoreb[i] - m0) * inv;
}

// ---------------- pooled[d] = sum_g w[g]*hn[g][d] ----------------
__global__ __launch_bounds__(256) void k_pooled() {
    int d = blockIdx.x;
    float acc = 0.f;
    for (int g = threadIdx.x; g < NB * L_TOK; g += 256)
        acc += g_wts[g] * g_hn[(long long)g * DM + d];
    acc = bsum(acc);
    if (threadIdx.x == 0) g_pooled[d] = acc;
}

// ---------------- final classifier + softmax ----------------
__global__ void k_final(const float* __restrict__ cls_w, const float* __restrict__ cls_b,
                        float* __restrict__ out, int out_size) {
    int tid = threadIdx.x;  // 64
    int cls = tid >> 5, lane = tid & 31;
    float acc = 0.f;
    for (int d = lane; d < DM; d += 32) acc += g_pooled[d] * cls_w[cls * DM + d];
    #pragma unroll
    for (int o = 16; o > 0; o >>= 1) acc += __shfl_xor_sync(0xffffffffu, acc, o);
    __shared__ float lg[2];
    if (lane == 0) lg[cls] = acc;
    __syncthreads();
    if (tid == 0) {
        float l0 = lg[0] + cls_b[0], l1 = lg[1] + cls_b[1];
        float m = fmaxf(l0, l1);
        float e0 = expf(l0 - m), e1 = expf(l1 - m);
        float s = e0 + e1;
        out[0] = l0;
        out[1] = l1;
        if (out_size >= 4) { out[2] = e0 / s; out[3] = e1 / s; }
    }
}

// ---------------- launch ----------------
extern "C" void kernel_launch(void* const* d_in, const int* in_sizes, int n_in,
                              void* d_out, int out_size) {
    const float* x        = (const float*)d_in[0];
    const float* fc1_w    = (const float*)d_in[1];
    const float* fc1_b    = (const float*)d_in[2];
    const float* in_proj_w= (const float*)d_in[3];
    const float* conv_w   = (const float*)d_in[4];
    const float* conv_b   = (const float*)d_in[5];
    const float* dt_bias  = (const float*)d_in[6];
    const float* A_log    = (const float*)d_in[7];
    const float* Dh       = (const float*)d_in[8];
    const float* norm_w   = (const float*)d_in[9];
    const float* out_proj_w=(const float*)d_in[10];
    const float* ln_w     = (const float*)d_in[11];
    const float* ln_b     = (const float*)d_in[12];
    const float* attn_w1  = (const float*)d_in[13];
    const float* attn_b1  = (const float*)d_in[14];
    const float* attn_w2  = (const float*)d_in[15];
    const float* attn_b2  = (const float*)d_in[16];
    const float* cls_w    = (const float*)d_in[17];
    const float* cls_b    = (const float*)d_in[18];
    float* out = (float*)d_out;

    void *p_hbase, *p_hcur, *p_zx, *p_y, *p_hn, *p_s1;
    cudaGetSymbolAddress(&p_hbase, g_hbase);
    cudaGetSymbolAddress(&p_hcur,  g_hcur);
    cudaGetSymbolAddress(&p_zx,    g_zx);
    cudaGetSymbolAddress(&p_y,     g_y);
    cudaGetSymbolAddress(&p_hn,    g_hn);
    cudaGetSymbolAddress(&p_s1,    g_s1);

    cudaFuncSetAttribute(k_intra, cudaFuncAttributeMaxDynamicSharedMemorySize, SMEM_INTRA);

    // fc1: h = relu(x @ fc1_w^T + b)
    {
        dim3 grid((DM + 63) / 64, (L_TOK + 127) / 128, 1);
        tgemm<<<grid, 256>>>(x, 0, fc1_w, 0, fc1_b, (float*)p_hbase, 0,
                             L_TOK, DM, 1024, 2, 0);
    }
    k_prep<<<(int)(((long long)L_TOK * DM + 255) / 256), 256>>>((const float*)p_hbase, (float*)p_hcur);
    k_zeropad<<<(NB * (LP - L_TOK) * DM + 255) / 256, 256>>>((float*)p_hcur);

    for (int j = 0; j < 2; j++) {
        // in_proj: zxbcdt = h @ in_w^T (per-branch weight 2b+j)
        {
            dim3 g1((DPROJ + 63) / 64, (LP + 127) / 128, NB);
            tgemm<<<g1, 256>>>((const float*)p_hcur, (long long)LP * DM,
                               in_proj_w, (long long)DPROJ * DM, nullptr,
                               (float*)p_zx, (long long)LP * DPROJ,
                               LP, DPROJ, DM, 0, j);
        }
        k_conv<<<dim3(LP, NB), 128>>>(conv_w, conv_b, j);
        k_dt<<<(int)(((long long)NB * LP * NH + 255) / 256), 256>>>(dt_bias, A_log, j);
        k_cumsum<<<dim3(NC, NH, NB), 64>>>();
        k_intra<<<dim3(NC, NH, NB), 256, SMEM_INTRA>>>();
        k_rec<<<NB * NH, 256>>>();
        k_inter<<<dim3(NC, NH, NB), 256>>>(Dh, j);
        k_gate<<<dim3(LP, NB), 256>>>(norm_w, j);
        // out_proj + residual accumulate
        {
            dim3 g2((DM + 63) / 64, (LP + 127) / 128, NB);
            tgemm<<<g2, 256>>>((const float*)p_y, (long long)LP * DI,
                               out_proj_w, (long long)DM * DI, nullptr,
                               (float*)p_hcur, (long long)LP * DM,
                               LP, DM, DI, 1, j);
        }
    }

    // final head
    k_ln<<<NB * L_TOK, 256>>>(ln_w, ln_b);
    {
        dim3 ga((128 + 63) / 64, (NB * L_TOK + 127) / 128, 1);
        tgemm<<<ga, 256>>>((const float*)p_hn, 0, attn_w1, 0, attn_b1,
                           (float*)p_s1, 0, NB * L_TOK, 128, DM, 3, 0);
    }
    k_score<<<NB * L_TOK, 128>>>(attn_w2, attn_b2);
    k_softmax<<<1, 1024>>>();
    k_pooled<<<DM, 256>>>();
    k_final<<<1, 64>>>(cls_w, cls_b, out, out_size);
}

// round 4
// speedup vs baseline: 1.3895x; 1.3895x over previous
#include <cuda_runtime.h>
#include <cuda_bf16.h>
#include <math.h>

// ---------------- problem constants ----------------
#define L_TOK 10000
#define LP    10048          // 157 * 64 (padded length)
#define NC    157            // chunks
#define Q     64             // chunk length
#define DM    512
#define DI    1024
#define DS    64
#define NH    16
#define HD    64
#define DXBC  1152
#define DPROJ 2192
#define NB    3              // branches

// ---------------- scratch (device globals, no allocation) ----------------
__device__ __align__(16) float g_hbase[(size_t)L_TOK*DM];
__device__ __align__(16) float g_hcur [(size_t)NB*LP*DM];
__device__ __align__(16) float g_zx   [(size_t)NB*LP*DPROJ];
__device__ __align__(16) float g_xs   [(size_t)NB*LP*DI];
__device__ __align__(16) float g_Bm   [(size_t)NB*LP*DS];
__device__ __align__(16) float g_Cm   [(size_t)NB*LP*DS];
__device__ __align__(16) float g_dtv  [(size_t)NB*LP*NH];
__device__ __align__(16) float g_av   [(size_t)NB*NH*LP];
__device__ __align__(16) float g_cum  [(size_t)NB*NH*LP];
__device__ __align__(16) float g_y    [(size_t)NB*LP*DI];
__device__ __align__(16) float g_schunk[(size_t)NB*NH*NC*DS*HD];
__device__ __align__(16) float g_sbef  [(size_t)NB*NH*NC*DS*HD];
__device__ __align__(16) float g_hn   [(size_t)NB*L_TOK*DM];
__device__ __align__(16) float g_s1   [(size_t)NB*L_TOK*128];
__device__ float g_scoreb[NB*L_TOK];
__device__ float g_wts   [NB*L_TOK];
__device__ float g_pooled[DM];

// ---------------- helpers ----------------
__device__ __forceinline__ float bsum(float v) {
    __shared__ float sh[32];
    int lane = threadIdx.x & 31, w = threadIdx.x >> 5;
    #pragma unroll
    for (int o = 16; o > 0; o >>= 1) v += __shfl_xor_sync(0xffffffffu, v, o);
    if (lane == 0) sh[w] = v;
    __syncthreads();
    int nw = blockDim.x >> 5;
    v = (threadIdx.x < nw) ? sh[threadIdx.x] : 0.f;
    if (w == 0) {
        #pragma unroll
        for (int o = 16; o > 0; o >>= 1) v += __shfl_xor_sync(0xffffffffu, v, o);
        if (threadIdx.x == 0) sh[0] = v;
    }
    __syncthreads();
    float r = sh[0];
    __syncthreads();
    return r;
}

// ---------------- bf16 split helpers ----------------
// pack two consecutive-k fp32 values into {hi bf16x2, lo bf16x2}
__device__ __forceinline__ uint2 split_bf16_pair(float f0, float f1) {
    unsigned hp, lp;
    asm("cvt.rn.bf16x2.f32 %0, %1, %2;" : "=r"(hp) : "f"(f1), "f"(f0));
    __nv_bfloat162 h = *reinterpret_cast<__nv_bfloat162*>(&hp);
    float r0 = f0 - __bfloat162float(h.x);
    float r1 = f1 - __bfloat162float(h.y);
    asm("cvt.rn.bf16x2.f32 %0, %1, %2;" : "=r"(lp) : "f"(r1), "f"(r0));
    uint2 q; q.x = hp; q.y = lp;
    return q;
}

__device__ __forceinline__ void mma16(float c[4], const unsigned a[4], const unsigned b[2]) {
    asm volatile(
        "mma.sync.aligned.m16n8k16.row.col.f32.bf16.bf16.f32 "
        "{%0,%1,%2,%3},{%4,%5,%6,%7},{%8,%9},{%0,%1,%2,%3};"
        : "+f"(c[0]), "+f"(c[1]), "+f"(c[2]), "+f"(c[3])
        : "r"(a[0]), "r"(a[1]), "r"(a[2]), "r"(a[3]), "r"(b[0]), "r"(b[1]));
}

// ---------------- tensor-core GEMM: C = A(MxK) @ W(NxK)^T (split-bf16 x3) ----------------
// smem holds uint2{hi bf16x2, lo bf16x2} pairs along k. One k16 step per tile.
// op: 0 = store, 1 = C += , 2 = relu(v+bias), 3 = tanh(v+bias)
// per-z: A += z*sA, C += z*sC, W += (2*z+joff)*sW
// tiles: BM=128, BN=64, BK=16, 256 threads = 8 warps (4 m-warps x 2 n-warps)
#define APADU 132
#define WPADU 68
__global__ __launch_bounds__(256, 2) void tgemm(
    const float* __restrict__ A, long long sA,
    const float* __restrict__ W, long long sW,
    const float* __restrict__ bias,
    float* __restrict__ C, long long sC,
    int M, int N, int K, int op, int joff)
{
    int z = blockIdx.z;
    A += (long long)z * sA;
    C += (long long)z * sC;
    W += (long long)(2 * z + joff) * sW;

    __shared__ uint2 As[2][8][APADU];   // [kpair][m]
    __shared__ uint2 Ws[2][8][WPADU];   // [kpair][n]

    int tid = threadIdx.x;
    int warp = tid >> 5, lane = tid & 31;
    int wm = warp & 3, wn = warp >> 2;
    int g = lane >> 2, tig = lane & 3;
    int row0 = blockIdx.y * 128, col0 = blockIdx.x * 64;

    // ldg indexing
    int ar = tid >> 1, apb = (tid & 1) * 4;      // A: row, k-pair base (4 pairs = 8 floats)
    int wr = tid >> 2, wpb = (tid & 3) * 2;      // W: row(n), k-pair base (2 pairs = 4 floats)
    bool aok = (row0 + ar) < M;
    bool wok = (col0 + wr) < N;
    const float* Aptr = A + (long long)(row0 + ar) * K + apb * 2;
    const float* Wptr = W + (long long)(col0 + wr) * K + wpb * 2;

    float c[2][4][4];
    #pragma unroll
    for (int mt = 0; mt < 2; mt++)
        #pragma unroll
        for (int nt = 0; nt < 4; nt++)
            #pragma unroll
            for (int q = 0; q < 4; q++) c[mt][nt][q] = 0.f;

    float4 pa0, pa1, pw;
    const float4 zero4 = make_float4(0.f, 0.f, 0.f, 0.f);

    // load tile 0
    pa0 = aok ? *(const float4*)(Aptr)     : zero4;
    pa1 = aok ? *(const float4*)(Aptr + 4) : zero4;
    pw  = wok ? *(const float4*)(Wptr)     : zero4;
    As[0][apb + 0][ar] = split_bf16_pair(pa0.x, pa0.y);
    As[0][apb + 1][ar] = split_bf16_pair(pa0.z, pa0.w);
    As[0][apb + 2][ar] = split_bf16_pair(pa1.x, pa1.y);
    As[0][apb + 3][ar] = split_bf16_pair(pa1.z, pa1.w);
    Ws[0][wpb + 0][wr] = split_bf16_pair(pw.x, pw.y);
    Ws[0][wpb + 1][wr] = split_bf16_pair(pw.z, pw.w);
    __syncthreads();

    int nK = K >> 4;
    for (int kt = 0; kt < nK; kt++) {
        int cur = kt & 1;
        bool pf = (kt + 1) < nK;
        if (pf) {
            const float* Ap = Aptr + (kt + 1) * 16;
            const float* Wp = Wptr + (kt + 1) * 16;
            pa0 = aok ? *(const float4*)(Ap)     : zero4;
            pa1 = aok ? *(const float4*)(Ap + 4) : zero4;
            pw  = wok ? *(const float4*)(Wp)     : zero4;
        }

        // fragment loads (one k16 step)
        uint2 qa[2][4];
        #pragma unroll
        for (int mt = 0; mt < 2; mt++) {
            int m0 = wm * 32 + mt * 16;
            qa[mt][0] = As[cur][tig    ][m0 + g    ];
            qa[mt][1] = As[cur][tig    ][m0 + g + 8];
            qa[mt][2] = As[cur][tig + 4][m0 + g    ];
            qa[mt][3] = As[cur][tig + 4][m0 + g + 8];
        }
        uint2 qb[4][2];
        #pragma unroll
        for (int nt = 0; nt < 4; nt++) {
            int n0 = wn * 32 + nt * 8;
            qb[nt][0] = Ws[cur][tig    ][n0 + g];
            qb[nt][1] = Ws[cur][tig + 4][n0 + g];
        }
        unsigned ahi[2][4], alo[2][4];
        #pragma unroll
        for (int mt = 0; mt < 2; mt++)
            #pragma unroll
            for (int q = 0; q < 4; q++) { ahi[mt][q] = qa[mt][q].x; alo[mt][q] = qa[mt][q].y; }
        unsigned bhi[4][2], blo[4][2];
        #pragma unroll
        for (int nt = 0; nt < 4; nt++)
            #pragma unroll
            for (int q = 0; q < 2; q++) { bhi[nt][q] = qb[nt][q].x; blo[nt][q] = qb[nt][q].y; }

        #pragma unroll
        for (int mt = 0; mt < 2; mt++)
            #pragma unroll
            for (int nt = 0; nt < 4; nt++) {
                mma16(c[mt][nt], alo[mt], bhi[nt]);
                mma16(c[mt][nt], ahi[mt], blo[nt]);
                mma16(c[mt][nt], ahi[mt], bhi[nt]);
            }

        if (pf) {
            int nxt = 1 - cur;
            As[nxt][apb + 0][ar] = split_bf16_pair(pa0.x, pa0.y);
            As[nxt][apb + 1][ar] = split_bf16_pair(pa0.z, pa0.w);
            As[nxt][apb + 2][ar] = split_bf16_pair(pa1.x, pa1.y);
            As[nxt][apb + 3][ar] = split_bf16_pair(pa1.z, pa1.w);
            Ws[nxt][wpb + 0][wr] = split_bf16_pair(pw.x, pw.y);
            Ws[nxt][wpb + 1][wr] = split_bf16_pair(pw.z, pw.w);
            __syncthreads();
        }
    }

    // epilogue
    #pragma unroll
    for (int mt = 0; mt < 2; mt++) {
        #pragma unroll
        for (int nt = 0; nt < 4; nt++) {
            int cc = col0 + wn * 32 + nt * 8 + 2 * tig;
            if (cc >= N) continue;
            #pragma unroll
            for (int half = 0; half < 2; half++) {
                int r = row0 + wm * 32 + mt * 16 + g + half * 8;
                if (r >= M) continue;
                float v0 = c[mt][nt][half * 2 + 0];
                float v1 = c[mt][nt][half * 2 + 1];
                long long ci = (long long)r * N + cc;
                if (op == 0) {
                    *(float2*)&C[ci] = make_float2(v0, v1);
                } else if (op == 1) {
                    float2 o = *(float2*)&C[ci];
                    o.x += v0; o.y += v1;
                    *(float2*)&C[ci] = o;
                } else if (op == 2) {
                    v0 += bias[cc]; v1 += bias[cc + 1];
                    *(float2*)&C[ci] = make_float2(v0 > 0.f ? v0 : 0.f, v1 > 0.f ? v1 : 0.f);
                } else {
                    v0 += bias[cc]; v1 += bias[cc + 1];
                    *(float2*)&C[ci] = make_float2(tanhf(v0), tanhf(v1));
                }
            }
        }
    }
}

// ---------------- prep: build 3 branch inputs ----------------
__global__ void k_prep(const float* __restrict__ hb, float* __restrict__ hcur) {
    long long i = (long long)blockIdx.x * 256 + threadIdx.x;
    if (i >= (long long)L_TOK * DM) return;
    int t = (int)(i >> 9);
    int d = (int)(i & 511);
    float v = hb[i];
    hcur[(long long)t * DM + d] = v;                                      // branch 0
    hcur[(long long)LP * DM + (long long)t * DM + (DM - 1 - d)] = v;      // branch 1: feature flip
    int tt = (t % 100) * 100 + t / 100;                                   // branch 2: grid transpose
    hcur[2LL * LP * DM + (long long)tt * DM + d] = v;
}

__global__ void k_zeropad(float* __restrict__ hcur) {
    int i = blockIdx.x * 256 + threadIdx.x;
    const int tot = NB * (LP - L_TOK) * DM;
    if (i >= tot) return;
    int b = i / ((LP - L_TOK) * DM);
    int r = i % ((LP - L_TOK) * DM);
    hcur[(long long)b * LP * DM + (long long)L_TOK * DM + r] = 0.f;
}

// ---------------- depthwise causal conv + silu + split ----------------
__global__ void k_conv(const float* __restrict__ cw, const float* __restrict__ cb, int j) {
    int t = blockIdx.x, b = blockIdx.y;
    int lidx = 2 * b + j;
    const float* base = g_zx + (long long)b * LP * DPROJ + DI;  // xBC slice
    long long tb = (long long)b * LP + t;
    for (int c = threadIdx.x; c < DXBC; c += blockDim.x) {
        float accv = cb[lidx * DXBC + c];
        #pragma unroll
        for (int k = 0; k < 4; k++) {
            int ttk = t - 3 + k;
            if (ttk >= 0)
                accv += base[(long long)ttk * DPROJ + c] * cw[(lidx * DXBC + c) * 4 + k];
        }
        float v = accv / (1.f + __expf(-accv));
        if (t >= L_TOK) v = 0.f;
        if (c < DI)            g_xs[tb * DI + c] = v;
        else if (c < DI + DS)  g_Bm[tb * DS + (c - DI)] = v;
        else                   g_Cm[tb * DS + (c - DI - DS)] = v;
    }
}

// ---------------- dt = softplus(dt_raw + bias), a = dt * A ----------------
__global__ void k_dt(const float* __restrict__ dt_bias, const float* __restrict__ A_log, int j) {
    long long idx = (long long)blockIdx.x * 256 + threadIdx.x;
    if (idx >= (long long)NB * LP * NH) return;
    int hd = (int)(idx % NH);
    int t  = (int)((idx / NH) % LP);
    int b  = (int)(idx / ((long long)NH * LP));
    int lidx = 2 * b + j;
    float draw = g_zx[((long long)b * LP + t) * DPROJ + DI + DXBC + hd];
    float xv = draw + dt_bias[lidx * NH + hd];
    float sp = (xv > 20.f) ? xv : log1pf(expf(xv));
    if (t >= L_TOK) sp = 0.f;
    float Ah = -expf(A_log[lidx * NH + hd]);
    g_dtv[((long long)b * LP + t) * NH + hd] = sp;
    g_av[((long long)(b * NH + hd)) * LP + t] = sp * Ah;
}

// ---------------- per-chunk inclusive cumsum of a ----------------
__global__ void k_cumsum() {
    int c = blockIdx.x, h = blockIdx.y, b = blockIdx.z;
    long long base = (long long)(b * NH + h) * LP + (long long)c * Q;
    int t = threadIdx.x;  // 64 threads
    float x = g_av[base + t];
    #pragma unroll
    for (int o = 1; o < 32; o <<= 1) {
        float yv = __shfl_up_sync(0xffffffffu, x, o);
        if ((t & 31) >= o) x += yv;
    }
    __shared__ float w0;
    if (t == 31) w0 = x;
    __syncthreads();
    if (t >= 32) x += w0;
    g_cum[base + t] = x;
}

#define SMEM_INTRA ((4 * 64 * 65 + 64) * 4)

// ---------------- intra-chunk attention-like kernel + chunk state ----------------
__global__ __launch_bounds__(256) void k_intra() {
    extern __shared__ float sm[];
    float* sC   = sm;
    float* sB   = sm + 64 * 65;
    float* sU   = sm + 2 * 64 * 65;
    float* sP   = sm + 3 * 64 * 65;
    float* scum = sm + 4 * 64 * 65;

    int c = blockIdx.x, h = blockIdx.y, b = blockIdx.z;
    long long rowb = (long long)b * LP + (long long)c * Q;
    int tid = threadIdx.x;

    for (int i = tid; i < 4096; i += 256) {
        int t = i >> 6, n = i & 63;
        sC[t * 65 + n] = g_Cm[(rowb + t) * DS + n];
        sB[t * 65 + n] = g_Bm[(rowb + t) * DS + n];
        sU[t * 65 + n] = g_dtv[(rowb + t) * NH + h] * g_xs[(rowb + t) * DI + h * HD + n];
    }
    if (tid < 64) scum[tid] = g_cum[(long long)(b * NH + h) * LP + (long long)c * Q + tid];
    __syncthreads();

    int tx = tid & 15, ty = tid >> 4;
    int r0 = ty * 4, c0 = tx * 4;

    // P = mask(exp) * (C @ B^T)
    {
        float acc[4][4];
        #pragma unroll
        for (int i = 0; i < 4; i++) { acc[i][0]=0.f; acc[i][1]=0.f; acc[i][2]=0.f; acc[i][3]=0.f; }
        for (int n = 0; n < 64; n++) {
            float cv[4], bv[4];
            #pragma unroll
            for (int i = 0; i < 4; i++) cv[i] = sC[(r0 + i) * 65 + n];
            #pragma unroll
            for (int j = 0; j < 4; j++) bv[j] = sB[(c0 + j) * 65 + n];
            #pragma unroll
            for (int i = 0; i < 4; i++)
                #pragma unroll
                for (int j = 0; j < 4; j++) acc[i][j] += cv[i] * bv[j];
        }
        #pragma unroll
        for (int i = 0; i < 4; i++)
            #pragma unroll
            for (int j = 0; j < 4; j++) {
                int t = r0 + i, s = c0 + j;
                sP[t * 65 + s] = (s <= t) ? acc[i][j] * __expf(scum[t] - scum[s]) : 0.f;
            }
    }
    __syncthreads();

    // Y_intra = P @ U
    {
        float accY[4][4];
        #pragma unroll
        for (int i = 0; i < 4; i++) { accY[i][0]=0.f; accY[i][1]=0.f; accY[i][2]=0.f; accY[i][3]=0.f; }
        for (int s = 0; s < 64; s++) {
            float pv[4], uv[4];
            #pragma unroll
            for (int i = 0; i < 4; i++) pv[i] = sP[(r0 + i) * 65 + s];
            #pragma unroll
            for (int j = 0; j < 4; j++) uv[j] = sU[s * 65 + c0 + j];
            #pragma unroll
            for (int i = 0; i < 4; i++)
                #pragma unroll
                for (int j = 0; j < 4; j++) accY[i][j] += pv[i] * uv[j];
        }
        #pragma unroll
        for (int i = 0; i < 4; i++)
            #pragma unroll
            for (int j = 0; j < 4; j++)
                g_y[(rowb + r0 + i) * DI + h * HD + c0 + j] = accY[i][j];
    }

    // S_chunk[n][p] = sum_s exp(T - cum_s) B[s][n] U[s][p]
    {
        float T = scum[63];
        float accS[4][4];
        #pragma unroll
        for (int i = 0; i < 4; i++) { accS[i][0]=0.f; accS[i][1]=0.f; accS[i][2]=0.f; accS[i][3]=0.f; }
        for (int s = 0; s < 64; s++) {
            float w = __expf(T - scum[s]);
            float bv[4], uv[4];
            #pragma unroll
            for (int i = 0; i < 4; i++) bv[i] = sB[s * 65 + r0 + i] * w;
            #pragma unroll
            for (int j = 0; j < 4; j++) uv[j] = sU[s * 65 + c0 + j];
            #pragma unroll
            for (int i = 0; i < 4; i++)
                #pragma unroll
                for (int j = 0; j < 4; j++) accS[i][j] += bv[i] * uv[j];
        }
        long long sbase = ((long long)(b * NH + h) * NC + c) * 4096;
        #pragma unroll
        for (int i = 0; i < 4; i++)
            #pragma unroll
            for (int j = 0; j < 4; j++)
                g_schunk[sbase + (r0 + i) * 64 + c0 + j] = accS[i][j];
    }
}

// ---------------- sequential chunk-state recurrence (only sequential part) ----------------
__global__ __launch_bounds__(256) void k_rec() {
    int bh = blockIdx.x;          // 0..47
    int tid = threadIdx.x;        // 256
    float S[16];
    #pragma unroll
    for (int i = 0; i < 16; i++) S[i] = 0.f;
    const float* cumrow = g_cum + (long long)bh * LP;
    for (int c = 0; c < NC; c++) {
        long long base = ((long long)bh * NC + c) * 4096;
        float e = __expf(cumrow[c * Q + 63]);
        #pragma unroll
        for (int i = 0; i < 16; i++) {
            int idx = tid + i * 256;
            g_sbef[base + idx] = S[i];
            S[i] = e * S[i] + g_schunk[base + idx];
        }
    }
}

// ---------------- inter-chunk contribution + Dh*x ----------------
__global__ __launch_bounds__(256) void k_inter(const float* __restrict__ Dh, int j) {
    __shared__ float sS[64 * 65];
    __shared__ float sC[64 * 65];
    __shared__ float scum[64];
    int c = blockIdx.x, h = blockIdx.y, b = blockIdx.z;
    long long rowb = (long long)b * LP + (long long)c * Q;
    int tid = threadIdx.x;
    long long sbase = ((long long)(b * NH + h) * NC + c) * 4096;
    for (int i = tid; i < 4096; i += 256) {
        int r = i >> 6, n = i & 63;
        sS[r * 65 + n] = g_sbef[sbase + i];
        sC[r * 65 + n] = g_Cm[(rowb + r) * DS + n];
    }
    if (tid < 64) scum[tid] = g_cum[(long long)(b * NH + h) * LP + (long long)c * Q + tid];
    __syncthreads();

    int tx = tid & 15, ty = tid >> 4;
    int r0 = ty * 4, c0 = tx * 4;
    float acc[4][4];
    #pragma unroll
    for (int i = 0; i < 4; i++) { acc[i][0]=0.f; acc[i][1]=0.f; acc[i][2]=0.f; acc[i][3]=0.f; }
    for (int n = 0; n < 64; n++) {
        float cv[4], sv[4];
        #pragma unroll
        for (int i = 0; i < 4; i++) cv[i] = sC[(r0 + i) * 65 + n];
        #pragma unroll
        for (int jj = 0; jj < 4; jj++) sv[jj] = sS[n * 65 + c0 + jj];
        #pragma unroll
        for (int i = 0; i < 4; i++)
            #pragma unroll
            for (int jj = 0; jj < 4; jj++) acc[i][jj] += cv[i] * sv[jj];
    }
    float dh = Dh[(2 * b + j) * NH + h];
    #pragma unroll
    for (int i = 0; i < 4; i++) {
        float e = __expf(scum[r0 + i]);
        #pragma unroll
        for (int jj = 0; jj < 4; jj++) {
            long long ydx = (rowb + r0 + i) * DI + h * HD + c0 + jj;
            g_y[ydx] = g_y[ydx] + e * acc[i][jj] + dh * g_xs[ydx];
        }
    }
}

// ---------------- gate (silu(z)) + RMSNorm, in place on g_y ----------------
__global__ __launch_bounds__(256) void k_gate(const float* __restrict__ norm_w, int j) {
    int t = blockIdx.x, b = blockIdx.y;
    int lidx = 2 * b + j;
    const float* z = g_zx + ((long long)b * LP + t) * DPROJ;
    float* yr = g_y + ((long long)b * LP + t) * DI;
    float vals[4];
    float ss = 0.f;
    #pragma unroll
    for (int i = 0; i < 4; i++) {
        int cidx = threadIdx.x + i * 256;
        float zv = z[cidx];
        float gv = yr[cidx] * (zv / (1.f + __expf(-zv)));
        vals[i] = gv;
        ss += gv * gv;
    }
    float tot = bsum(ss);
    float scale = rsqrtf(tot / (float)DI + 1e-5f);
    #pragma unroll
    for (int i = 0; i < 4; i++) {
        int cidx = threadIdx.x + i * 256;
        yr[cidx] = vals[i] * scale * norm_w[lidx * DI + cidx];
    }
}

// ---------------- final LayerNorm over concat tokens ----------------
__global__ __launch_bounds__(256) void k_ln(const float* __restrict__ lnw, const float* __restrict__ lnb) {
    int g = blockIdx.x;          // 0..29999
    int b = g / L_TOK, t = g % L_TOK;
    const float* row = g_hcur + ((long long)b * LP + t) * DM;
    int tid = threadIdx.x;
    float v0 = row[tid], v1 = row[tid + 256];
    float s = bsum(v0 + v1);
    float sq = bsum(v0 * v0 + v1 * v1);
    float mu = s / (float)DM;
    float var = sq / (float)DM - mu * mu;
    float inv = rsqrtf(var + 1e-5f);
    g_hn[(long long)g * DM + tid]       = (v0 - mu) * inv * lnw[tid] + lnb[tid];
    g_hn[(long long)g * DM + tid + 256] = (v1 - mu) * inv * lnw[tid + 256] + lnb[tid + 256];
}

// ---------------- attention scalar score ----------------
__global__ void k_score(const float* __restrict__ w2, const float* __restrict__ b2) {
    int g = blockIdx.x;
    int tid = threadIdx.x;  // 128
    float v = g_s1[(long long)g * 128 + tid] * w2[tid];
    v = bsum(v);
    if (tid == 0) g_scoreb[g] = v + b2[0];
}

// ---------------- softmax over 30000 scores ----------------
__global__ void k_softmax() {
    const int n = NB * L_TOK;
    __shared__ float red[32];
    __shared__ float s_max, s_sum;
    int tid = threadIdx.x;  // 1024
    float m = -1e30f;
    for (int i = tid; i < n; i += 1024) m = fmaxf(m, g_scoreb[i]);
    #pragma unroll
    for (int o = 16; o > 0; o >>= 1) m = fmaxf(m, __shfl_xor_sync(0xffffffffu, m, o));
    if ((tid & 31) == 0) red[tid >> 5] = m;
    __syncthreads();
    if (tid < 32) {
        float v = red[tid];
        #pragma unroll
        for (int o = 16; o > 0; o >>= 1) v = fmaxf(v, __shfl_xor_sync(0xffffffffu, v, o));
        if (tid == 0) s_max = v;
    }
    __syncthreads();
    float m0 = s_max;
    float s = 0.f;
    for (int i = tid; i < n; i += 1024) s += expf(g_scoreb[i] - m0);
    #pragma unroll
    for (int o = 16; o > 0; o >>= 1) s += __shfl_xor_sync(0xffffffffu, s, o);
    if ((tid & 31) == 0) red[tid >> 5] = s;
    __syncthreads();
    if (tid < 32) {
        float v = red[tid];
        #pragma unroll
        for (int o = 16; o > 0; o >>= 1) v += __shfl_xor_sync(0xffffffffu, v, o);
        if (tid == 0) s_sum = v;
    }
    __syncthreads();
    float inv = 1.f / s_sum;
    for (int i = tid; i < n; i += 1024) g_wts[i] = expf(g_scoreb[i] - m0) * inv;
}

// ---------------- pooled[d] = sum_g w[g]*hn[g][d] ----------------
__global__ __launch_bounds__(256) void k_pooled() {
    int d = blockIdx.x;
    float acc = 0.f;
    for (int g = threadIdx.x; g < NB * L_TOK; g += 256)
        acc += g_wts[g] * g_hn[(long long)g * DM + d];
    acc = bsum(acc);
    if (threadIdx.x == 0) g_pooled[d] = acc;
}

// ---------------- final classifier + softmax ----------------
__global__ void k_final(const float* __restrict__ cls_w, const float* __restrict__ cls_b,
                        float* __restrict__ out, int out_size) {
    int tid = threadIdx.x;  // 64
    int cls = tid >> 5, lane = tid & 31;
    float acc = 0.f;
    for (int d = lane; d < DM; d += 32) acc += g_pooled[d] * cls_w[cls * DM + d];
    #pragma unroll
    for (int o = 16; o > 0; o >>= 1) acc += __shfl_xor_sync(0xffffffffu, acc, o);
    __shared__ float lg[2];
    if (lane == 0) lg[cls] = acc;
    __syncthreads();
    if (tid == 0) {
        float l0 = lg[0] + cls_b[0], l1 = lg[1] + cls_b[1];
        float m = fmaxf(l0, l1);
        float e0 = expf(l0 - m), e1 = expf(l1 - m);
        float s = e0 + e1;
        out[0] = l0;
        out[1] = l1;
        if (out_size >= 4) { out[2] = e0 / s; out[3] = e1 / s; }
    }
}

// ---------------- launch ----------------
extern "C" void kernel_launch(void* const* d_in, const int* in_sizes, int n_in,
                              void* d_out, int out_size) {
    const float* x        = (const float*)d_in[0];
    const float* fc1_w    = (const float*)d_in[1];
    const float* fc1_b    = (const float*)d_in[2];
    const float* in_proj_w= (const float*)d_in[3];
    const float* conv_w   = (const float*)d_in[4];
    const float* conv_b   = (const float*)d_in[5];
    const float* dt_bias  = (const float*)d_in[6];
    const float* A_log    = (const float*)d_in[7];
    const float* Dh       = (const float*)d_in[8];
    const float* norm_w   = (const float*)d_in[9];
    const float* out_proj_w=(const float*)d_in[10];
    const float* ln_w     = (const float*)d_in[11];
    const float* ln_b     = (const float*)d_in[12];
    const float* attn_w1  = (const float*)d_in[13];
    const float* attn_b1  = (const float*)d_in[14];
    const float* attn_w2  = (const float*)d_in[15];
    const float* attn_b2  = (const float*)d_in[16];
    const float* cls_w    = (const float*)d_in[17];
    const float* cls_b    = (const float*)d_in[18];
    float* out = (float*)d_out;

    void *p_hbase, *p_hcur, *p_zx, *p_y, *p_hn, *p_s1;
    cudaGetSymbolAddress(&p_hbase, g_hbase);
    cudaGetSymbolAddress(&p_hcur,  g_hcur);
    cudaGetSymbolAddress(&p_zx,    g_zx);
    cudaGetSymbolAddress(&p_y,     g_y);
    cudaGetSymbolAddress(&p_hn,    g_hn);
    cudaGetSymbolAddress(&p_s1,    g_s1);

    cudaFuncSetAttribute(k_intra, cudaFuncAttributeMaxDynamicSharedMemorySize, SMEM_INTRA);

    // fc1: h = relu(x @ fc1_w^T + b)
    {
        dim3 grid((DM + 63) / 64, (L_TOK + 127) / 128, 1);
        tgemm<<<grid, 256>>>(x, 0, fc1_w, 0, fc1_b, (float*)p_hbase, 0,
                             L_TOK, DM, 1024, 2, 0);
    }
    k_prep<<<(int)(((long long)L_TOK * DM + 255) / 256), 256>>>((const float*)p_hbase, (float*)p_hcur);
    k_zeropad<<<(NB * (LP - L_TOK) * DM + 255) / 256, 256>>>((float*)p_hcur);

    for (int j = 0; j < 2; j++) {
        // in_proj: zxbcdt = h @ in_w^T (per-branch weight 2b+j)
        {
            dim3 g1((DPROJ + 63) / 64, (LP + 127) / 128, NB);
            tgemm<<<g1, 256>>>((const float*)p_hcur, (long long)LP * DM,
                               in_proj_w, (long long)DPROJ * DM, nullptr,
                               (float*)p_zx, (long long)LP * DPROJ,
                               LP, DPROJ, DM, 0, j);
        }
        k_conv<<<dim3(LP, NB), 128>>>(conv_w, conv_b, j);
        k_dt<<<(int)(((long long)NB * LP * NH + 255) / 256), 256>>>(dt_bias, A_log, j);
        k_cumsum<<<dim3(NC, NH, NB), 64>>>();
        k_intra<<<dim3(NC, NH, NB), 256, SMEM_INTRA>>>();
        k_rec<<<NB * NH, 256>>>();
        k_inter<<<dim3(NC, NH, NB), 256>>>(Dh, j);
        k_gate<<<dim3(LP, NB), 256>>>(norm_w, j);
        // out_proj + residual accumulate
        {
            dim3 g2((DM + 63) / 64, (LP + 127) / 128, NB);
            tgemm<<<g2, 256>>>((const float*)p_y, (long long)LP * DI,
                               out_proj_w, (long long)DM * DI, nullptr,
                               (float*)p_hcur, (long long)LP * DM,
                               LP, DM, DI, 1, j);
        }
    }

    // final head
    k_ln<<<NB * L_TOK, 256>>>(ln_w, ln_b);
    {
        dim3 ga((128 + 63) / 64, (NB * L_TOK + 127) / 128, 1);
        tgemm<<<ga, 256>>>((const float*)p_hn, 0, attn_w1, 0, attn_b1,
                           (float*)p_s1, 0, NB * L_TOK, 128, DM, 3, 0);
    }
    k_score<<<NB * L_TOK, 128>>>(attn_w2, attn_b2);
    k_softmax<<<1, 1024>>>();
    k_pooled<<<DM, 256>>>();
    k_final<<<1, 64>>>(cls_w, cls_b, out, out_size);
}